// round 12
// baseline (speedup 1.0000x reference)
#include <cuda_runtime.h>
#include <cuda_fp16.h>
#include <cstdint>

#define VOCAB 50000
#define DIM   768
#define NTOK  16384
#define BM    128
#define BN    96
#define KCH   64                       // K per pipeline chunk (4 k16-steps)
#define NCH   (DIM / KCH)              // 12
#define NKS   (DIM / 16)               // 48 k16-steps per row
#define NM16  (NTOK / 16)              // 1024 fragment row-groups
#define NTILE_N (DIM / BN)             // 8
#define A_STAGE_BYTES (BM * KCH * 2)   // 16 KB (fp16)
#define B_STAGE_BYTES (BN * KCH * 2)   // 12 KB
#define STAGE_BYTES   (A_STAGE_BYTES + B_STAGE_BYTES)   // 28 KB
#define K_SMEM        (2 * STAGE_BYTES)   // 56 KB -> 2 CTAs/SM
#define GRID     296                   // persistent: 2 CTAs/SM, all resident
#define THREADS  192                   // 6 warps: 2(M) x 3(N), warp tile 64x32
#define COPY_ROWS 48                   // rows per copy work unit (8/warp)
#define NCOPY ((NTOK + COPY_ROWS - 1) / COPY_ROWS)   // 342

__device__ unsigned g_bar;            // monotonic barrier arrivals (init kernel resets)
__device__ int g_cnt;
__device__ int g_list[NTOK];          // token position (output row)
__device__ int g_tok[NTOK];           // token id (embedding row)
// Fragment-packed fp16 operands for mma.sync m16n8k16 (row.col)
__device__ uint4 Ap[NM16 * NKS * 32];
__device__ uint4 Wp[(DIM / 16) * NKS * 32];

// ---------------------------------------------------------------- utilities
__device__ __forceinline__ uint32_t f2h2(float x, float y) {
    __half2 h = __floats2half2_rn(x, y);
    return *(uint32_t*)&h;
}
__device__ __forceinline__ uint32_t smem_u32(const void* p) {
    uint32_t a;
    asm("{ .reg .u64 t; cvta.to.shared.u64 t, %1; cvt.u32.u64 %0, t; }" : "=r"(a) : "l"(p));
    return a;
}
__device__ __forceinline__ void cp16(uint32_t dst, const void* src) {
    asm volatile("cp.async.cg.shared.global [%0], [%1], 16;\n" :: "r"(dst), "l"(src));
}
__device__ __forceinline__ void mma_f16(float c[4], uint4 a, uint32_t b0, uint32_t b1) {
    asm volatile(
        "mma.sync.aligned.m16n8k16.row.col.f32.f16.f16.f32 "
        "{%0,%1,%2,%3}, {%4,%5,%6,%7}, {%8,%9}, {%0,%1,%2,%3};\n"
        : "+f"(c[0]), "+f"(c[1]), "+f"(c[2]), "+f"(c[3])
        : "r"(a.x), "r"(a.y), "r"(a.z), "r"(a.w), "r"(b0), "r"(b1));
}
// Grid-wide barrier: all GRID CTAs resident by construction; phase is the
// cumulative barrier index (1, 2, ...). g_bar reset to 0 by k_init each launch.
__device__ __forceinline__ void grid_barrier(int phase) {
    __syncthreads();
    if (threadIdx.x == 0) {
        __threadfence();
        atomicAdd(&g_bar, 1u);
        const unsigned target = (unsigned)phase * GRID;
        while (*(volatile unsigned*)&g_bar < target) { }
        __threadfence();
    }
    __syncthreads();
}

// ---------------------------------------------------------------- init
__global__ void k_init() { g_bar = 0; g_cnt = 0; }

// ---------------------------------------------------------------- the kernel
__global__ __launch_bounds__(THREADS, 2) void k_all(
    const int* __restrict__ token, const int* __restrict__ need,
    const float* __restrict__ emb, const float* __restrict__ W,
    const float* __restrict__ bias, float* __restrict__ out)
{
    extern __shared__ uint32_t smem[];   // 2 stages x (A 16KB | B 12KB)
    __shared__ int s_is64;

    const int bid  = blockIdx.x;
    const int tid  = threadIdx.x;
    const int lane = tid & 31;
    const int wid  = tid >> 5;           // 0..5

    // ---- phase 0a: per-CTA dtype detect (first 128 tokens; odd words all 0 => int64)
    int odd = (tid < 128) ? token[tid * 2 + 1] : 0;
    int any = __syncthreads_or(odd != 0);
    if (tid == 0) s_is64 = !any;
    __syncthreads();
    const int is64 = s_is64;

    // ---- phase 0b: compact (g_cnt pre-reset by k_init)
    for (int p = bid * THREADS + tid; p < NTOK; p += GRID * THREADS) {
        const int t = is64 ? token[2 * p] : token[p];
        if (t >= 0 && t < VOCAB && need[t]) {
            const int pos = atomicAdd(&g_cnt, 1);
            g_list[pos] = p;
            g_tok[pos]  = t;
        }
    }
    grid_barrier(1);
    const int cnt = g_cnt;
    const int cnt_pad = (cnt + BM - 1) & ~(BM - 1);

    // ---- phase 1: pack W (strided) + pack A (warp tasks)
    for (int gi = bid * THREADS + tid; gi < 48 * NKS * 32; gi += GRID * THREADS) {
        const int lw  = gi & 31;
        const int ks  = (gi >> 5) % NKS;
        const int n16 = gi / (NKS * 32);
        const int na = n16 * 16 + (lw >> 2);
        const int nb = na + 8;
        const int k0 = ks * 16 + (lw & 3) * 2;
        uint4 o;
        o.x = f2h2(W[(size_t)k0 * DIM + na],       W[(size_t)(k0 + 1) * DIM + na]);
        o.y = f2h2(W[(size_t)(k0 + 8) * DIM + na], W[(size_t)(k0 + 9) * DIM + na]);
        o.z = f2h2(W[(size_t)k0 * DIM + nb],       W[(size_t)(k0 + 1) * DIM + nb]);
        o.w = f2h2(W[(size_t)(k0 + 8) * DIM + nb], W[(size_t)(k0 + 9) * DIM + nb]);
        Wp[(size_t)(n16 * NKS + ks) * 32 + lw] = o;
    }
    // A pack: task = (m16, half); each warp-task covers 24 ksteps (12 iters x 2)
    {
        const int n_tasks = (cnt_pad / 16) * 2;
        for (int task = bid * 6 + wid; task < n_tasks; task += GRID * 6) {
            const int m16 = task >> 1, half = task & 1;
            const int lr = lane >> 2, lk = lane & 3;
            const int r0 = m16 * 16 + lr, r1 = r0 + 8;
            const bool v0 = r0 < cnt, v1 = r1 < cnt;
            const float* e0 = emb + (size_t)(v0 ? g_tok[r0] : 0) * DIM;
            const float* e1 = emb + (size_t)(v1 ? g_tok[r1] : 0) * DIM;
            const float2 z2 = make_float2(0.f, 0.f);
            #pragma unroll
            for (int j = 0; j < 24; j += 2) {
                const int ksA = half * 24 + j;
                const int kA = ksA * 16 + lk * 2;
                const int kB = kA + 16;
                const float2 a0 = v0 ? *(const float2*)(e0 + kA)     : z2;
                const float2 a2 = v0 ? *(const float2*)(e0 + kA + 8) : z2;
                const float2 a1 = v1 ? *(const float2*)(e1 + kA)     : z2;
                const float2 a3 = v1 ? *(const float2*)(e1 + kA + 8) : z2;
                const float2 b0 = v0 ? *(const float2*)(e0 + kB)     : z2;
                const float2 b2 = v0 ? *(const float2*)(e0 + kB + 8) : z2;
                const float2 b1 = v1 ? *(const float2*)(e1 + kB)     : z2;
                const float2 b3 = v1 ? *(const float2*)(e1 + kB + 8) : z2;
                uint4 oA, oB;
                oA.x = f2h2(a0.x, a0.y); oA.y = f2h2(a1.x, a1.y);
                oA.z = f2h2(a2.x, a2.y); oA.w = f2h2(a3.x, a3.y);
                oB.x = f2h2(b0.x, b0.y); oB.y = f2h2(b1.x, b1.y);
                oB.z = f2h2(b2.x, b2.y); oB.w = f2h2(b3.x, b3.y);
                Ap[(size_t)(m16 * NKS + ksA) * 32 + lane]     = oA;
                Ap[(size_t)(m16 * NKS + ksA + 1) * 32 + lane] = oB;
            }
        }
    }
    grid_barrier(2);

    // ---- phase 2: gemm tiles + copy units in one strided work loop
    const int n_mt = cnt_pad / BM;
    const int ntiles = n_mt * NTILE_N;
    const int wm2 = wid / 3;             // 0..1 (M)
    const int wn  = wid - wm2 * 3;       // 0..2 (N)

    #define ISSUE(c, s)                                                          \
    {                                                                            \
        const uint32_t dstA = smem_u32(smem) + (s) * STAGE_BYTES;                \
        const uint32_t dstB = dstA + A_STAGE_BYTES;                              \
        _Pragma("unroll")                                                        \
        for (int j = 0; j < 6; j++) {            /* A: 1024 x 16B */             \
            const int idx = tid + j * THREADS;                                   \
            if (idx < 1024) {                                                    \
                const int piece = idx >> 7, off = idx & 127;                     \
                const uint4* src =                                               \
                    Ap + (size_t)((mtile * 8 + piece) * NKS + (c) * 4) * 32 + off; \
                cp16(dstA + piece * 2048 + off * 16, src);                       \
            }                                                                    \
        }                                                                        \
        _Pragma("unroll")                                                        \
        for (int j = 0; j < 4; j++) {            /* B: 768 x 16B (exact) */      \
            const int idx = tid + j * THREADS;                                   \
            const int piece = idx >> 7, off = idx & 127;                         \
            const uint4* src =                                                   \
                Wp + (size_t)((n16_0 + piece) * NKS + (c) * 4) * 32 + off;       \
            cp16(dstB + piece * 2048 + off * 16, src);                           \
        }                                                                        \
        asm volatile("cp.async.commit_group;\n" ::: "memory");                   \
    }

    for (int w = bid; w < ntiles + NCOPY; w += GRID) {
        if (w < ntiles) {
            // ---------------- GEMM tile (identical config to R11)
            const int mtile = w / NTILE_N;
            const int nt    = w - mtile * NTILE_N;
            const int n16_0 = nt * (BN / 16);
            const int n0    = nt * BN;

            float acc[4][4][4];
            #pragma unroll
            for (int i = 0; i < 4; i++)
                #pragma unroll
                for (int j = 0; j < 4; j++)
                    #pragma unroll
                    for (int r = 0; r < 4; r++) acc[i][j][r] = 0.0f;

            ISSUE(0, 0)

            for (int c = 0; c < NCH; c++) {
                if (c + 1 < NCH) {
                    ISSUE(c + 1, (c + 1) & 1)
                    asm volatile("cp.async.wait_group 1;\n" ::: "memory");
                } else {
                    asm volatile("cp.async.wait_group 0;\n" ::: "memory");
                }
                __syncthreads();

                const uint32_t* aS = smem + (c & 1) * (STAGE_BYTES / 4);
                const uint32_t* bS = aS + (A_STAGE_BYTES / 4);
                #pragma unroll
                for (int ks = 0; ks < 4; ks++) {
                    uint4 a[4], b[2];
                    #pragma unroll
                    for (int fm = 0; fm < 4; fm++)
                        a[fm] = *(const uint4*)(aS + ((wm2 * 4 + fm) * 512 + ks * 128 + lane * 4));
                    #pragma unroll
                    for (int g = 0; g < 2; g++)
                        b[g] = *(const uint4*)(bS + ((wn * 2 + g) * 512 + ks * 128 + lane * 4));
                    #pragma unroll
                    for (int fm = 0; fm < 4; fm++) {
                        mma_f16(acc[fm][0], a[fm], b[0].x, b[0].y);
                        mma_f16(acc[fm][1], a[fm], b[0].z, b[0].w);
                        mma_f16(acc[fm][2], a[fm], b[1].x, b[1].y);
                        mma_f16(acc[fm][3], a[fm], b[1].z, b[1].w);
                    }
                }
                __syncthreads();
            }

            // epilogue: bias + scatter
            #pragma unroll
            for (int fm = 0; fm < 4; fm++) {
                const int r0 = mtile * BM + wm2 * 64 + fm * 16 + (lane >> 2);
                const int r1 = r0 + 8;
                #pragma unroll
                for (int fn = 0; fn < 4; fn++) {
                    const int g = fn >> 1, sub = fn & 1;
                    const int col = n0 + (wn * 2 + g) * 16 + sub * 8 + (lane & 3) * 2;
                    const float b0 = bias[col], b1 = bias[col + 1];
                    if (r0 < cnt) {
                        const int p = g_list[r0];
                        float2 v = make_float2(acc[fm][fn][0] + b0, acc[fm][fn][1] + b1);
                        *(float2*)&out[(size_t)p * DIM + col] = v;
                    }
                    if (r1 < cnt) {
                        const int p = g_list[r1];
                        float2 v = make_float2(acc[fm][fn][2] + b0, acc[fm][fn][3] + b1);
                        *(float2*)&out[(size_t)p * DIM + col] = v;
                    }
                }
            }
        } else {
            // ---------------- copy unit: 48 rows, 8 rows per warp
            const int base = (w - ntiles) * COPY_ROWS + wid * 8;
            #pragma unroll 1
            for (int r = 0; r < 8; r++) {
                const int p = base + r;
                if (p >= NTOK) break;
                const int t = is64 ? token[2 * p] : token[p];
                if (t < 0 || t >= VOCAB) continue;
                if (need[t]) continue;               // GEMM wrote these rows
                const float4* src = (const float4*)(emb + (size_t)t * DIM);
                float4* dst = (float4*)(out + (size_t)p * DIM);
                float4 v0 = src[lane];
                float4 v1 = src[lane + 32];
                float4 v2 = src[lane + 64];
                float4 v3 = src[lane + 96];
                float4 v4 = src[lane + 128];
                float4 v5 = src[lane + 160];
                dst[lane]       = v0;
                dst[lane + 32]  = v1;
                dst[lane + 64]  = v2;
                dst[lane + 96]  = v3;
                dst[lane + 128] = v4;
                dst[lane + 160] = v5;
            }
        }
    }
    #undef ISSUE
}

// ---------------------------------------------------------------- launch
extern "C" void kernel_launch(void* const* d_in, const int* in_sizes, int n_in,
                              void* d_out, int out_size) {
    const int*   token = (const int*)d_in[0];   // int32 or int64 (auto-detected)
    const int*   need  = (const int*)d_in[1];
    const float* emb   = (const float*)d_in[2];
    const float* W     = (const float*)d_in[3];
    const float* bias  = (const float*)d_in[4];
    float*       out   = (float*)d_out;

    cudaFuncSetAttribute(k_all, cudaFuncAttributeMaxDynamicSharedMemorySize, K_SMEM);

    k_init<<<1, 1>>>();
    k_all<<<GRID, THREADS, K_SMEM>>>(token, need, emb, W, bias, out);
}

// round 13
// speedup vs baseline: 1.5871x; 1.5871x over previous
#include <cuda_runtime.h>
#include <cuda_fp16.h>
#include <cstdint>

#define VOCAB 50000
#define DIM   768
#define NTOK  16384
#define BM    128
#define BN    96
#define KCH   64                       // K per pipeline chunk (4 k16-steps)
#define NCH   (DIM / KCH)              // 12
#define NKS   (DIM / 16)               // 48 k16-steps per row
#define NM16  (NTOK / 16)              // 1024 fragment row-groups
#define NTILE_N (DIM / BN)             // 8
#define A_STAGE_BYTES (BM * KCH * 2)   // 16 KB (fp16)
#define B_STAGE_BYTES (BN * KCH * 2)   // 12 KB
#define STAGE_BYTES   (A_STAGE_BYTES + B_STAGE_BYTES)   // 28 KB
#define GEMM_SMEM     (2 * STAGE_BYTES)   // 56 KB -> 2 CTAs/SM
#define GEMM_GRID     296              // persistent: 2 CTAs/SM
#define GEMM_THREADS  192              // 6 warps: 2(M) x 3(N), warp tile 64x32
#define COPY_ROWS 48                   // rows per copy work unit (8/warp, 6 warps)
#define NCOPY ((NTOK + COPY_ROWS - 1) / COPY_ROWS)   // 342

// pack-kernel block ranges
#define NB_PACK  (NM16 / 2)            // 512: 2 m16-groups per block
#define NB_WPACK ((48 * NKS * 32) / 256)  // 288
#define NB_PTOT  (NB_PACK + NB_WPACK)

__device__ int g_cnt;
__device__ int g_tok64;               // 1 if token buffer is int64
__device__ int g_list[NTOK];          // token position (output row)
__device__ int g_tok[NTOK];           // token id (embedding row)
// Fragment-packed fp16 operands for mma.sync m16n8k16 (row.col)
__device__ uint4 Ap[NM16 * NKS * 32];
__device__ uint4 Wp[(DIM / 16) * NKS * 32];

// ---------------------------------------------------------------- utilities
__device__ __forceinline__ uint32_t f2h2(float x, float y) {
    __half2 h = __floats2half2_rn(x, y);
    return *(uint32_t*)&h;
}
__device__ __forceinline__ uint32_t smem_u32(const void* p) {
    uint32_t a;
    asm("{ .reg .u64 t; cvta.to.shared.u64 t, %1; cvt.u32.u64 %0, t; }" : "=r"(a) : "l"(p));
    return a;
}
__device__ __forceinline__ void cp16(uint32_t dst, const void* src) {
    asm volatile("cp.async.cg.shared.global [%0], [%1], 16;\n" :: "r"(dst), "l"(src));
}
__device__ __forceinline__ void mma_f16(float c[4], uint4 a, uint32_t b0, uint32_t b1) {
    asm volatile(
        "mma.sync.aligned.m16n8k16.row.col.f32.f16.f16.f32 "
        "{%0,%1,%2,%3}, {%4,%5,%6,%7}, {%8,%9}, {%0,%1,%2,%3};\n"
        : "+f"(c[0]), "+f"(c[1]), "+f"(c[2]), "+f"(c[3])
        : "r"(a.x), "r"(a.y), "r"(a.z), "r"(a.w), "r"(b0), "r"(b1));
}

// ---------------------------------------------------------------- init
__global__ void k_init() { g_cnt = 0; }

// ---------------------------------------------------------------- compact (+detect)
// 64 blocks x 256: per-block dtype detect (L2-hot), then 1 token per thread.
__global__ void k_compact(const int* __restrict__ token, const int* __restrict__ need) {
    const int tid = threadIdx.x;
    int odd = (tid < 128) ? token[tid * 2 + 1] : 0;
    int any = __syncthreads_or(odd != 0);
    const int is64 = !any;
    if (blockIdx.x == 0 && tid == 0) g_tok64 = is64;

    const int p = blockIdx.x * 256 + tid;          // grid covers NTOK exactly
    const int t = is64 ? token[2 * p] : token[p];
    if (t >= 0 && t < VOCAB && need[t]) {
        const int pos = atomicAdd(&g_cnt, 1);
        g_list[pos] = p;
        g_tok[pos]  = t;
    }
}

// ---------------------------------------------------------------- pack
// Blocks [0,NB_PACK): A fragment pack (2 m16-groups x 4 warps each).
// Blocks [NB_PACK,NB_PTOT): W fragment pack.
__global__ void k_pack(const float* __restrict__ emb, const float* __restrict__ W) {
    const int bid  = blockIdx.x;
    const int tid  = threadIdx.x;
    const int wid  = tid >> 5;
    const int lane = tid & 31;

    if (bid < NB_PACK) {
        const int cnt = g_cnt;
        const int cnt_pad = (cnt + BM - 1) & ~(BM - 1);
        const int m16 = bid * 2 + (wid >> 2);
        if (m16 * 16 >= cnt_pad) return;
        const int wg = wid & 3;                      // warp within group
        const int lr = lane >> 2, lk = lane & 3;
        const int r0 = m16 * 16 + lr, r1 = r0 + 8;
        const bool v0 = r0 < cnt, v1 = r1 < cnt;
        const float* e0 = emb + (size_t)(v0 ? g_tok[r0] : 0) * DIM;
        const float* e1 = emb + (size_t)(v1 ? g_tok[r1] : 0) * DIM;
        const float2 z2 = make_float2(0.f, 0.f);
        #pragma unroll
        for (int j = 0; j < NKS / 4; j += 2) {       // 12 ksteps, 2 at a time
            const int ksA = wg * (NKS / 4) + j;
            const int kA = ksA * 16 + lk * 2;
            const int kB = kA + 16;
            const float2 a0 = v0 ? *(const float2*)(e0 + kA)     : z2;
            const float2 a2 = v0 ? *(const float2*)(e0 + kA + 8) : z2;
            const float2 a1 = v1 ? *(const float2*)(e1 + kA)     : z2;
            const float2 a3 = v1 ? *(const float2*)(e1 + kA + 8) : z2;
            const float2 b0 = v0 ? *(const float2*)(e0 + kB)     : z2;
            const float2 b2 = v0 ? *(const float2*)(e0 + kB + 8) : z2;
            const float2 b1 = v1 ? *(const float2*)(e1 + kB)     : z2;
            const float2 b3 = v1 ? *(const float2*)(e1 + kB + 8) : z2;
            uint4 oA, oB;
            oA.x = f2h2(a0.x, a0.y); oA.y = f2h2(a1.x, a1.y);
            oA.z = f2h2(a2.x, a2.y); oA.w = f2h2(a3.x, a3.y);
            oB.x = f2h2(b0.x, b0.y); oB.y = f2h2(b1.x, b1.y);
            oB.z = f2h2(b2.x, b2.y); oB.w = f2h2(b3.x, b3.y);
            Ap[(size_t)(m16 * NKS + ksA) * 32 + lane]     = oA;
            Ap[(size_t)(m16 * NKS + ksA + 1) * 32 + lane] = oB;
        }
    } else {
        const int gi = (bid - NB_PACK) * 256 + tid;  // 48*48*32
        const int lw  = gi & 31;
        const int ks  = (gi >> 5) % NKS;
        const int n16 = gi / (NKS * 32);
        const int na = n16 * 16 + (lw >> 2);
        const int nb = na + 8;
        const int k0 = ks * 16 + (lw & 3) * 2;
        uint4 o;
        o.x = f2h2(W[(size_t)k0 * DIM + na],       W[(size_t)(k0 + 1) * DIM + na]);
        o.y = f2h2(W[(size_t)(k0 + 8) * DIM + na], W[(size_t)(k0 + 9) * DIM + na]);
        o.z = f2h2(W[(size_t)k0 * DIM + nb],       W[(size_t)(k0 + 1) * DIM + nb]);
        o.w = f2h2(W[(size_t)(k0 + 8) * DIM + nb], W[(size_t)(k0 + 9) * DIM + nb]);
        Wp[(size_t)(n16 * NKS + ks) * 32 + lw] = o;
    }
}

// ---------------------------------------------------------------- GEMM + copy
// Persistent CTAs; work loop = GEMM tiles (ntile fastest) then copy units.
// Copy units fill DRAM-idle time / tile-count imbalance of the GEMM.
__global__ __launch_bounds__(GEMM_THREADS, 2) void k_gemm(
    const int* __restrict__ token, const int* __restrict__ need,
    const float* __restrict__ emb, const float* __restrict__ bias,
    float* __restrict__ out)
{
    const int cnt = g_cnt;
    const int is64 = g_tok64;
    const int cnt_pad = (cnt + BM - 1) & ~(BM - 1);
    const int n_mt = cnt_pad / BM;
    const int ntiles = n_mt * NTILE_N;

    extern __shared__ uint32_t smem[];   // 2 stages x (A 16KB | B 12KB)

    const int tid  = threadIdx.x;
    const int lane = tid & 31;
    const int wid  = tid >> 5;           // 0..5
    const int wm2  = wid / 3;            // 0..1 (M)
    const int wn   = wid - wm2 * 3;      // 0..2 (N)

    #define ISSUE(c, s)                                                          \
    {                                                                            \
        const uint32_t dstA = smem_u32(smem) + (s) * STAGE_BYTES;                \
        const uint32_t dstB = dstA + A_STAGE_BYTES;                              \
        _Pragma("unroll")                                                        \
        for (int j = 0; j < 6; j++) {            /* A: 1024 x 16B */             \
            const int idx = tid + j * GEMM_THREADS;                              \
            if (idx < 1024) {                                                    \
                const int piece = idx >> 7, off = idx & 127;                     \
                const uint4* src =                                               \
                    Ap + (size_t)((mtile * 8 + piece) * NKS + (c) * 4) * 32 + off; \
                cp16(dstA + piece * 2048 + off * 16, src);                       \
            }                                                                    \
        }                                                                        \
        _Pragma("unroll")                                                        \
        for (int j = 0; j < 4; j++) {            /* B: 768 x 16B (exact) */      \
            const int idx = tid + j * GEMM_THREADS;                              \
            const int piece = idx >> 7, off = idx & 127;                         \
            const uint4* src =                                                   \
                Wp + (size_t)((n16_0 + piece) * NKS + (c) * 4) * 32 + off;       \
            cp16(dstB + piece * 2048 + off * 16, src);                           \
        }                                                                        \
        asm volatile("cp.async.commit_group;\n" ::: "memory");                   \
    }

    for (int w = blockIdx.x; w < ntiles + NCOPY; w += GEMM_GRID) {
        if (w < ntiles) {
            // ---------------- GEMM tile (R11 config, unchanged)
            const int mtile = w / NTILE_N;
            const int nt    = w - mtile * NTILE_N;
            const int n16_0 = nt * (BN / 16);
            const int n0    = nt * BN;

            float acc[4][4][4];
            #pragma unroll
            for (int i = 0; i < 4; i++)
                #pragma unroll
                for (int j = 0; j < 4; j++)
                    #pragma unroll
                    for (int r = 0; r < 4; r++) acc[i][j][r] = 0.0f;

            ISSUE(0, 0)

            for (int c = 0; c < NCH; c++) {
                if (c + 1 < NCH) {
                    ISSUE(c + 1, (c + 1) & 1)
                    asm volatile("cp.async.wait_group 1;\n" ::: "memory");
                } else {
                    asm volatile("cp.async.wait_group 0;\n" ::: "memory");
                }
                __syncthreads();

                const uint32_t* aS = smem + (c & 1) * (STAGE_BYTES / 4);
                const uint32_t* bS = aS + (A_STAGE_BYTES / 4);
                #pragma unroll
                for (int ks = 0; ks < 4; ks++) {
                    uint4 a[4], b[2];
                    #pragma unroll
                    for (int fm = 0; fm < 4; fm++)
                        a[fm] = *(const uint4*)(aS + ((wm2 * 4 + fm) * 512 + ks * 128 + lane * 4));
                    #pragma unroll
                    for (int g = 0; g < 2; g++)
                        b[g] = *(const uint4*)(bS + ((wn * 2 + g) * 512 + ks * 128 + lane * 4));
                    #pragma unroll
                    for (int fm = 0; fm < 4; fm++) {
                        mma_f16(acc[fm][0], a[fm], b[0].x, b[0].y);
                        mma_f16(acc[fm][1], a[fm], b[0].z, b[0].w);
                        mma_f16(acc[fm][2], a[fm], b[1].x, b[1].y);
                        mma_f16(acc[fm][3], a[fm], b[1].z, b[1].w);
                    }
                }
                __syncthreads();
            }

            // epilogue: bias + scatter
            #pragma unroll
            for (int fm = 0; fm < 4; fm++) {
                const int r0 = mtile * BM + wm2 * 64 + fm * 16 + (lane >> 2);
                const int r1 = r0 + 8;
                #pragma unroll
                for (int fn = 0; fn < 4; fn++) {
                    const int g = fn >> 1, sub = fn & 1;
                    const int col = n0 + (wn * 2 + g) * 16 + sub * 8 + (lane & 3) * 2;
                    const float b0 = bias[col], b1 = bias[col + 1];
                    if (r0 < cnt) {
                        const int p = g_list[r0];
                        float2 v = make_float2(acc[fm][fn][0] + b0, acc[fm][fn][1] + b1);
                        *(float2*)&out[(size_t)p * DIM + col] = v;
                    }
                    if (r1 < cnt) {
                        const int p = g_list[r1];
                        float2 v = make_float2(acc[fm][fn][2] + b0, acc[fm][fn][3] + b1);
                        *(float2*)&out[(size_t)p * DIM + col] = v;
                    }
                }
            }
        } else {
            // ---------------- copy unit: 48 rows, 8 rows per warp
            const int base = (w - ntiles) * COPY_ROWS + wid * 8;
            #pragma unroll 1
            for (int r = 0; r < 8; r++) {
                const int p = base + r;
                if (p >= NTOK) break;
                const int t = is64 ? token[2 * p] : token[p];
                if (t < 0 || t >= VOCAB) continue;
                if (need[t]) continue;               // GEMM wrote these rows
                const float4* src = (const float4*)(emb + (size_t)t * DIM);
                float4* dst = (float4*)(out + (size_t)p * DIM);
                float4 v0 = src[lane];
                float4 v1 = src[lane + 32];
                float4 v2 = src[lane + 64];
                float4 v3 = src[lane + 96];
                float4 v4 = src[lane + 128];
                float4 v5 = src[lane + 160];
                dst[lane]       = v0;
                dst[lane + 32]  = v1;
                dst[lane + 64]  = v2;
                dst[lane + 96]  = v3;
                dst[lane + 128] = v4;
                dst[lane + 160] = v5;
            }
        }
    }
    #undef ISSUE
}

// ---------------------------------------------------------------- launch
extern "C" void kernel_launch(void* const* d_in, const int* in_sizes, int n_in,
                              void* d_out, int out_size) {
    const int*   token = (const int*)d_in[0];   // int32 or int64 (auto-detected)
    const int*   need  = (const int*)d_in[1];
    const float* emb   = (const float*)d_in[2];
    const float* W     = (const float*)d_in[3];
    const float* bias  = (const float*)d_in[4];
    float*       out   = (float*)d_out;

    cudaFuncSetAttribute(k_gemm, cudaFuncAttributeMaxDynamicSharedMemorySize, GEMM_SMEM);

    k_init<<<1, 1>>>();
    k_compact<<<NTOK / 256, 256>>>(token, need);
    k_pack<<<NB_PTOT, 256>>>(emb, W);
    k_gemm<<<GEMM_GRID, GEMM_THREADS, GEMM_SMEM>>>(token, need, emb, bias, out);
}